// round 2
// baseline (speedup 1.0000x reference)
#include <cuda_runtime.h>
#include <math.h>

#define D1 64
#define D2 16
#define DB 6
#define NMAX 250000
#define EMAX 2000000
#define GMAX 8192
#define NEMB 24

// ---------------- scratch (static device allocations, allowed) ----------------
__device__ float    g_h1[NMAX * D1];      // 64 MB
__device__ float    g_h2[NMAX * D2];      // 16 MB
__device__ float    g_gate[NMAX];
__device__ float    g_egate[NMAX];
__device__ unsigned g_gmax[GMAX];
__device__ float    g_gsum[GMAX];
__device__ float    g_emb[GMAX * D2];
__device__ float    g_tabA1[NEMB * D1];   // embeds @ W_neg1[:64] + b_neg1
__device__ float    g_tabR1[NEMB * D1];   // tanh(embeds @ W_root1 + b_root1)
__device__ float    g_meansum[1];

// ordered-uint mapping for float atomicMax (monotonic for all finite floats)
__device__ __forceinline__ unsigned fkey(float f) {
    unsigned b = __float_as_uint(f);
    return (b & 0x80000000u) ? ~b : (b | 0x80000000u);
}
__device__ __forceinline__ float funkey(unsigned u) {
    unsigned b = (u & 0x80000000u) ? (u ^ 0x80000000u) : ~u;
    return __uint_as_float(b);
}

// ---------------- K0: precompute conv1 tables ----------------
__global__ void k_tables(const float* __restrict__ embeds,
                         const float* __restrict__ Wn1, const float* __restrict__ bn1,
                         const float* __restrict__ Wr1, const float* __restrict__ br1) {
    int t = threadIdx.x;
    for (int idx = t; idx < NEMB * D1; idx += blockDim.x) {
        int c = idx / D1, f = idx % D1;
        float a = bn1[f], r = br1[f];
        for (int k = 0; k < D1; k++) {
            float e = embeds[c * D1 + k];
            a += e * Wn1[k * D1 + f];
            r += e * Wr1[k * D1 + f];
        }
        g_tabA1[idx] = a;
        g_tabR1[idx] = tanhf(r);
    }
}

// ---------------- K_init: zero per-call accumulators ----------------
__global__ void k_init(int G) {
    int i = blockIdx.x * blockDim.x + threadIdx.x;
    if (i == 0) g_meansum[0] = 0.f;
    if (i < G) { g_gmax[i] = 0u; g_gsum[i] = 0.f; }
    if (i < G * D2) g_emb[i] = 0.f;
}

// ---------------- K1: h1 root part via table ----------------
__global__ void k_h1_init(const int* __restrict__ x, int N) {
    int t = blockIdx.x * blockDim.x + threadIdx.x;
    if (t >= N * D1) return;
    int i = t >> 6, f = t & 63;
    g_h1[t] = g_tabR1[x[i] * D1 + f];
}

// ---------------- K2: conv1 edge pass (scatter-add) ----------------
#define K2_EPB 128
__global__ void __launch_bounds__(256)
k_conv1_edges(const int* __restrict__ ei, const float* __restrict__ ea,
              const int* __restrict__ x, const float* __restrict__ Wn1, int E) {
    __shared__ float sTab[NEMB * D1];
    __shared__ float sEA[K2_EPB * DB];
    __shared__ int   sDst[K2_EPB];
    __shared__ int   sC[K2_EPB];
    int t = threadIdx.x;
    for (int i = t; i < NEMB * D1; i += 256) sTab[i] = g_tabA1[i];
    int e0 = blockIdx.x * K2_EPB;
    int nE = min(K2_EPB, E - e0);
    if (t < nE) {
        sDst[t] = ei[e0 + t];
        sC[t]   = x[ei[E + e0 + t]];
    }
    for (int i = t; i < nE * DB; i += 256) sEA[i] = ea[e0 * DB + i];

    int f = t & 63;
    float wb[DB];
#pragma unroll
    for (int k = 0; k < DB; k++) wb[k] = Wn1[(D1 + k) * D1 + f];
    __syncthreads();

    for (int p = 0; p < K2_EPB / 4; p++) {
        int el = p * 4 + (t >> 6);
        if (el < nE) {
            int c = sC[el];
            float v = sTab[c * D1 + f];
#pragma unroll
            for (int k = 0; k < DB; k++) v += sEA[el * DB + k] * wb[k];
            v = tanhf(v);
            atomicAdd(&g_h1[sDst[el] * D1 + f], v);
        }
    }
}

// ---------------- K3: h2 root part (64 -> 16 per node) ----------------
#define K3_NPB 16
__global__ void __launch_bounds__(256)
k_h2_root(const float* __restrict__ Wr2, const float* __restrict__ br2, int N) {
    __shared__ float sW[D1 * D2];
    __shared__ float sH[K3_NPB][D1 + 4];
    int t = threadIdx.x;
    for (int i = t; i < D1 * D2; i += 256) sW[i] = Wr2[i];
    int n0 = blockIdx.x * K3_NPB;
    int nN = min(K3_NPB, N - n0);
    for (int i = t; i < nN * D1; i += 256)
        sH[i >> 6][i & 63] = g_h1[n0 * D1 + i];
    __syncthreads();
    int node = t >> 4, f = t & 15;
    if (node < nN) {
        float acc = br2[f];
#pragma unroll
        for (int k = 0; k < D1; k++) acc += sH[node][k] * sW[k * D2 + f];
        g_h2[(n0 + node) * D2 + f] = tanhf(acc);
    }
}

// ---------------- K4: conv2 edge pass (gather h1, 70->16, scatter) ----------------
#define K4_EPB 32
__global__ void __launch_bounds__(256)
k_conv2_edges(const int* __restrict__ ei, const float* __restrict__ ea,
              const float* __restrict__ Wn2, const float* __restrict__ bn2, int E) {
    __shared__ float sW[(D1 + DB) * D2];  // 70 x 16
    __shared__ float sH[K4_EPB][68];
    __shared__ float sEA[K4_EPB * DB];
    __shared__ int   sDst[K4_EPB];
    __shared__ int   sNb[K4_EPB];
    int t = threadIdx.x;
    for (int i = t; i < (D1 + DB) * D2; i += 256) sW[i] = Wn2[i];
    int e0 = blockIdx.x * K4_EPB;
    int nE = min(K4_EPB, E - e0);
    if (t < nE) {
        sDst[t] = ei[e0 + t];
        sNb[t]  = ei[E + e0 + t];
    }
    for (int i = t; i < nE * DB; i += 256) sEA[i] = ea[e0 * DB + i];
    __syncthreads();
    // gather neighbor rows (float4-coalesced)
    for (int i = t; i < nE * 16; i += 256) {
        int el = i >> 4, c4 = i & 15;
        float4 v = *(const float4*)&g_h1[sNb[el] * D1 + c4 * 4];
        *(float4*)&sH[el][c4 * 4] = v;
    }
    __syncthreads();
    int f = t & 15;
#pragma unroll
    for (int p = 0; p < 2; p++) {
        int el = p * 16 + (t >> 4);
        if (el < nE) {
            float acc = bn2[f];
#pragma unroll
            for (int k4 = 0; k4 < 16; k4++) {
                float4 h = *(const float4*)&sH[el][k4 * 4];
                acc += h.x * sW[(k4 * 4 + 0) * D2 + f];
                acc += h.y * sW[(k4 * 4 + 1) * D2 + f];
                acc += h.z * sW[(k4 * 4 + 2) * D2 + f];
                acc += h.w * sW[(k4 * 4 + 3) * D2 + f];
            }
#pragma unroll
            for (int k = 0; k < DB; k++) acc += sEA[el * DB + k] * sW[(D1 + k) * D2 + f];
            atomicAdd(&g_h2[sDst[el] * D2 + f], tanhf(acc));
        }
    }
}

// ---------------- K5: gate MLP 16->64->32->1 + segment max + mean sum ----------------
#define K5_NPB 32
__global__ void __launch_bounds__(256)
k_gate(const float* __restrict__ Wg1, const float* __restrict__ bg1,
       const float* __restrict__ Wg2, const float* __restrict__ bg2,
       const float* __restrict__ Wg3, const float* __restrict__ bg3,
       const int* __restrict__ batch, int N) {
    __shared__ float sW1[16 * 64];
    __shared__ float sW2[64 * 32];
    __shared__ float sW3[32];
    __shared__ float sB1[64], sB2[32];
    __shared__ float sH[K5_NPB][17];
    __shared__ float sG1[K5_NPB][65];
    __shared__ float sG2[K5_NPB][33];
    int t = threadIdx.x;
    for (int i = t; i < 1024; i += 256) sW1[i] = Wg1[i];
    for (int i = t; i < 2048; i += 256) sW2[i] = Wg2[i];
    if (t < 32) sW3[t] = Wg3[t];
    if (t < 64) sB1[t] = bg1[t];
    if (t < 32) sB2[t] = bg2[t];
    int n0 = blockIdx.x * K5_NPB;
    int nN = min(K5_NPB, N - n0);
    for (int i = t; i < nN * 16; i += 256) sH[i >> 4][i & 15] = g_h2[n0 * 16 + i];
    __syncthreads();
    // phase 1: 32 x 64 hidden
    {
        int f = t & 63;
        int r0 = (t >> 6) * 8;
#pragma unroll
        for (int r = 0; r < 8; r++) {
            int n = r0 + r;
            if (n < nN) {
                float acc = sB1[f];
#pragma unroll
                for (int k = 0; k < 16; k++) acc += sH[n][k] * sW1[k * 64 + f];
                sG1[n][f] = fmaxf(acc, 0.f);
            }
        }
    }
    __syncthreads();
    // phase 2: 32 x 32 hidden
    {
        int f2 = t & 31;
        int q0 = (t >> 5) * 4;
#pragma unroll
        for (int r = 0; r < 4; r++) {
            int n = q0 + r;
            if (n < nN) {
                float acc = sB2[f2];
#pragma unroll
                for (int j = 0; j < 64; j++) acc += sG1[n][j] * sW2[j * 32 + f2];
                sG2[n][f2] = fmaxf(acc, 0.f);
            }
        }
    }
    __syncthreads();
    // phase 3: gate scalar per node (warp 0 only)
    if (t < 32) {
        float gv = 0.f;
        if (t < nN) {
            float acc = bg3[0];
#pragma unroll
            for (int j = 0; j < 32; j++) acc += sG2[t][j] * sW3[j];
            gv = acc;
            int i = n0 + t;
            g_gate[i] = acc;
            atomicMax(&g_gmax[batch[i]], fkey(acc));
        }
        // warp-reduce sum for mean
        float s = gv;
#pragma unroll
        for (int off = 16; off > 0; off >>= 1) s += __shfl_xor_sync(0xffffffffu, s, off);
        if (t == 0) atomicAdd(&g_meansum[0], s);
    }
}

// ---------------- K6: exp(gate - max), segment sums, att output ----------------
__global__ void k_soft1(const int* __restrict__ batch, int N, float invN,
                        float* __restrict__ d_att) {
    int i = blockIdx.x * blockDim.x + threadIdx.x;
    if (i >= N) return;
    float g = g_gate[i];
    int b = batch[i];
    float m = funkey(g_gmax[b]);
    float e = expf(g - m);
    g_egate[i] = e;
    atomicAdd(&g_gsum[b], e);
    d_att[i] = g - g_meansum[0] * invN;
}

// ---------------- K7: attention-weighted embedding scatter ----------------
__global__ void k_scatter_emb(const int* __restrict__ batch, int N) {
    int t = blockIdx.x * blockDim.x + threadIdx.x;
    if (t >= N * D2) return;
    int i = t >> 4, f = t & 15;
    int b = batch[i];
    float w = g_egate[i] / (g_gsum[b] + 1e-16f);
    atomicAdd(&g_emb[b * D2 + f], w * g_h2[t]);
}

// ---------------- K8: head: 16->200 + BN + 200->1 + sigmoid ----------------
__global__ void __launch_bounds__(256)
k_final(const float* __restrict__ Wsemi, const float* __restrict__ gamma,
        const float* __restrict__ beta, const float* __restrict__ bmean,
        const float* __restrict__ bvar, const float* __restrict__ Wf,
        const float* __restrict__ bf,
        float* __restrict__ outv, float* __restrict__ sigv,
        float* __restrict__ out1, int G) {
    __shared__ float sE[16];
    __shared__ float red[256];
    int g = blockIdx.x, t = threadIdx.x;
    if (t < 16) sE[t] = g_emb[g * 16 + t];
    __syncthreads();
    float part = 0.f;
    if (t < 200) {
        float acc = 0.f;
#pragma unroll
        for (int k = 0; k < 16; k++) acc += sE[k] * Wsemi[k * 200 + t];
        float o = (acc - bmean[t]) * rsqrtf(bvar[t] + 1e-5f) * gamma[t] + beta[t];
        out1[g * 200 + t] = o;
        part = o * Wf[t];
    }
    red[t] = part;
    __syncthreads();
    for (int s = 128; s > 0; s >>= 1) {
        if (t < s) red[t] += red[t + s];
        __syncthreads();
    }
    if (t == 0) {
        float o = red[0] + bf[0];
        outv[g] = o;
        sigv[g] = 1.f / (1.f + expf(-o));
    }
}

// ---------------- launch ----------------
extern "C" void kernel_launch(void* const* d_in, const int* in_sizes, int n_in,
                              void* d_out, int out_size) {
    // num_graphs may appear as a size-1 int input at position 4
    int idx = (in_sizes[4] == 1) ? 5 : 4;
    const int*   x      = (const int*)d_in[0];
    const int*   ei     = (const int*)d_in[1];
    const float* ea     = (const float*)d_in[2];
    const int*   batch  = (const int*)d_in[3];
    const float* embeds = (const float*)d_in[idx + 0];
    const float* Wn1 = (const float*)d_in[idx + 1];  const float* bn1 = (const float*)d_in[idx + 2];
    const float* Wr1 = (const float*)d_in[idx + 3];  const float* br1 = (const float*)d_in[idx + 4];
    const float* Wn2 = (const float*)d_in[idx + 5];  const float* bn2 = (const float*)d_in[idx + 6];
    const float* Wr2 = (const float*)d_in[idx + 7];  const float* br2 = (const float*)d_in[idx + 8];
    const float* Wg1 = (const float*)d_in[idx + 9];  const float* bg1 = (const float*)d_in[idx + 10];
    const float* Wg2 = (const float*)d_in[idx + 11]; const float* bg2 = (const float*)d_in[idx + 12];
    const float* Wg3 = (const float*)d_in[idx + 13]; const float* bg3 = (const float*)d_in[idx + 14];
    const float* Wsemi = (const float*)d_in[idx + 15];
    const float* gamma = (const float*)d_in[idx + 16];
    const float* beta  = (const float*)d_in[idx + 17];
    const float* bmean = (const float*)d_in[idx + 18];
    const float* bvar  = (const float*)d_in[idx + 19];
    const float* Wf    = (const float*)d_in[idx + 20];
    const float* bf    = (const float*)d_in[idx + 21];

    int N = in_sizes[0];
    int E = in_sizes[1] / 2;
    int G = (out_size - N) / 202;  // out, sigmoid, att, out_1(200)

    float* outv = (float*)d_out;
    float* sigv = outv + G;
    float* att  = outv + 2 * G;
    float* out1 = att + N;

    k_tables<<<1, 256>>>(embeds, Wn1, bn1, Wr1, br1);
    int initN = G * D2;
    k_init<<<(initN + 255) / 256, 256>>>(G);
    k_h1_init<<<(N * D1 + 255) / 256, 256>>>(x, N);
    k_conv1_edges<<<(E + K2_EPB - 1) / K2_EPB, 256>>>(ei, ea, x, Wn1, E);
    k_h2_root<<<(N + K3_NPB - 1) / K3_NPB, 256>>>(Wr2, br2, N);
    k_conv2_edges<<<(E + K4_EPB - 1) / K4_EPB, 256>>>(ei, ea, Wn2, bn2, E);
    k_gate<<<(N + K5_NPB - 1) / K5_NPB, 256>>>(Wg1, bg1, Wg2, bg2, Wg3, bg3, batch, N);
    k_soft1<<<(N + 255) / 256, 256>>>(batch, N, 1.f / (float)N, att);
    k_scatter_emb<<<(N * D2 + 255) / 256, 256>>>(batch, N);
    k_final<<<G, 256>>>(Wsemi, gamma, beta, bmean, bvar, Wf, bf, outv, sigv, out1, G);
}

// round 3
// speedup vs baseline: 1.0802x; 1.0802x over previous
#include <cuda_runtime.h>
#include <math.h>

#define D1 64
#define D2 16
#define DB 6
#define NMAX 250000
#define EMAX 2000000
#define GMAX 8192
#define NEMB 24

// ---------------- scratch ----------------
__device__ float    g_h1[NMAX * D1];      // 64 MB
__device__ float    g_h2[NMAX * D2];      // 16 MB
__device__ float    g_gate[NMAX];
__device__ float    g_egate[NMAX];
__device__ unsigned g_gmax[GMAX];
__device__ float    g_gsum[GMAX];
__device__ float    g_emb[GMAX * D2];
__device__ float    g_tabA1[NEMB * D1];   // embeds @ W_neg1[:64] + b_neg1
__device__ float    g_tabR1[NEMB * D1];   // tanh(embeds @ W_root1 + b_root1)
__device__ float    g_meansum[1];

// ---------------- helpers ----------------
__device__ __forceinline__ float tanha(float x) {
    float y;
    asm("tanh.approx.f32 %0, %1;" : "=f"(y) : "f"(x));
    return y;
}
__device__ __forceinline__ void red4(float* p, float4 v) {
    asm volatile("red.global.add.v4.f32 [%0], {%1,%2,%3,%4};"
                 :: "l"(p), "f"(v.x), "f"(v.y), "f"(v.z), "f"(v.w) : "memory");
}
__device__ __forceinline__ unsigned fkey(float f) {
    unsigned b = __float_as_uint(f);
    return (b & 0x80000000u) ? ~b : (b | 0x80000000u);
}
__device__ __forceinline__ float funkey(unsigned u) {
    unsigned b = (u & 0x80000000u) ? (u ^ 0x80000000u) : ~u;
    return __uint_as_float(b);
}

// ---------------- K0: precompute conv1 tables ----------------
__global__ void k_tables(const float* __restrict__ embeds,
                         const float* __restrict__ Wn1, const float* __restrict__ bn1,
                         const float* __restrict__ Wr1, const float* __restrict__ br1) {
    int t = threadIdx.x;
    for (int idx = t; idx < NEMB * D1; idx += blockDim.x) {
        int c = idx / D1, f = idx % D1;
        float a = bn1[f], r = br1[f];
        for (int k = 0; k < D1; k++) {
            float e = embeds[c * D1 + k];
            a += e * Wn1[k * D1 + f];
            r += e * Wr1[k * D1 + f];
        }
        g_tabA1[idx] = a;
        g_tabR1[idx] = tanhf(r);
    }
}

// ---------------- K_init ----------------
__global__ void k_init(int G) {
    int i = blockIdx.x * blockDim.x + threadIdx.x;
    if (i == 0) g_meansum[0] = 0.f;
    if (i < G) { g_gmax[i] = 0u; g_gsum[i] = 0.f; }
    if (i < G * D2) g_emb[i] = 0.f;
}

// ---------------- K1: h1 root part (float4) ----------------
__global__ void k_h1_init(const int* __restrict__ x, int N) {
    int t = blockIdx.x * blockDim.x + threadIdx.x;
    if (t >= N * 16) return;
    ((float4*)g_h1)[t] = ((const float4*)g_tabR1)[x[t >> 4] * 16 + (t & 15)];
}

// ---------------- K2: conv1 edge pass ----------------
#define K2_EPB 64
__global__ void __launch_bounds__(256)
k_conv1_edges(const int* __restrict__ ei, const float* __restrict__ ea,
              const int* __restrict__ x, const float* __restrict__ Wn1, int E) {
    __shared__ float4 sTab[NEMB * 16];
    __shared__ float4 sWbS[DB * 16];
    __shared__ float  sEA[K2_EPB][DB];
    __shared__ int    sDst[K2_EPB];
    __shared__ int    sC[K2_EPB];
    int t = threadIdx.x;
    const float4* tab4 = (const float4*)g_tabA1;
    for (int i = t; i < NEMB * 16; i += 256) sTab[i] = tab4[i];
    const float4* wb4 = (const float4*)(Wn1 + D1 * D1);
    if (t < DB * 16) sWbS[t] = wb4[t];
    int e0 = blockIdx.x * K2_EPB;
    int nE = min(K2_EPB, E - e0);
    if (t < nE) {
        sDst[t] = ei[e0 + t];
        sC[t]   = x[ei[E + e0 + t]];
    }
    for (int i = t; i < nE * DB; i += 256) sEA[i / DB][i % DB] = ea[e0 * DB + i];
    __syncthreads();

    int q = t & 15;
    float4 wb[DB];
#pragma unroll
    for (int k = 0; k < DB; k++) wb[k] = sWbS[k * 16 + q];

#pragma unroll
    for (int p = 0; p < 4; p++) {
        int el = p * 16 + (t >> 4);
        if (el < nE) {
            float4 v = sTab[sC[el] * 16 + q];
#pragma unroll
            for (int k = 0; k < DB; k++) {
                float a = sEA[el][k];
                v.x += a * wb[k].x; v.y += a * wb[k].y;
                v.z += a * wb[k].z; v.w += a * wb[k].w;
            }
            v.x = tanha(v.x); v.y = tanha(v.y);
            v.z = tanha(v.z); v.w = tanha(v.w);
            red4(&g_h1[(size_t)sDst[el] * D1 + q * 4], v);
        }
    }
}

// ---------------- K3: h2 root (register weights) ----------------
#define K3_NPB 64
__global__ void __launch_bounds__(256, 2)
k_h2_root(const float* __restrict__ Wr2, const float* __restrict__ br2, int N) {
    __shared__ float4 sH[K3_NPB * 16];
    int t = threadIdx.x;
    int f = t & 15;
    float w[64];
#pragma unroll
    for (int k = 0; k < 64; k++) w[k] = Wr2[k * D2 + f];
    float bias = br2[f];
    int n0 = blockIdx.x * K3_NPB;
    int nN = min(K3_NPB, N - n0);
    const float4* h1v = (const float4*)g_h1;
    for (int i = t; i < nN * 16; i += 256) sH[i] = h1v[(size_t)n0 * 16 + i];
    __syncthreads();
#pragma unroll
    for (int p = 0; p < 4; p++) {
        int node = p * 16 + (t >> 4);
        if (node < nN) {
            float acc = bias;
#pragma unroll
            for (int k4 = 0; k4 < 16; k4++) {
                float4 h = sH[node * 16 + k4];
                acc += h.x * w[k4 * 4 + 0]; acc += h.y * w[k4 * 4 + 1];
                acc += h.z * w[k4 * 4 + 2]; acc += h.w * w[k4 * 4 + 3];
            }
            g_h2[(size_t)(n0 + node) * D2 + f] = tanhf(acc);
        }
    }
}

// ---------------- K4: conv2 edge pass (register weights, v4 RED) ----------------
#define K4_EPB 64
__global__ void __launch_bounds__(256, 2)
k_conv2_edges(const int* __restrict__ ei, const float* __restrict__ ea,
              const float* __restrict__ Wn2, const float* __restrict__ bn2, int E) {
    __shared__ float4 sH[K4_EPB * 16];
    __shared__ float  sEA[K4_EPB][DB];
    __shared__ int    sDst[K4_EPB];
    __shared__ int    sNb[K4_EPB];
    int t = threadIdx.x;
    int f = t & 15;
    float w[70];
#pragma unroll
    for (int k = 0; k < 70; k++) w[k] = Wn2[k * D2 + f];
    float bias = bn2[f];

    int e0 = blockIdx.x * K4_EPB;
    int nE = min(K4_EPB, E - e0);
    if (t < nE) {
        sDst[t] = ei[e0 + t];
        sNb[t]  = ei[E + e0 + t];
    }
    for (int i = t; i < nE * DB; i += 256) sEA[i / DB][i % DB] = ea[e0 * DB + i];
    __syncthreads();
    const float4* h1v = (const float4*)g_h1;
    for (int i = t; i < nE * 16; i += 256) {
        int el = i >> 4, c4 = i & 15;
        sH[i] = h1v[(size_t)sNb[el] * 16 + c4];
    }
    __syncthreads();
#pragma unroll
    for (int p = 0; p < 4; p++) {
        int el = p * 16 + (t >> 4);
        int elc = min(el, nE - 1);
        float acc = bias;
#pragma unroll
        for (int k4 = 0; k4 < 16; k4++) {
            float4 h = sH[elc * 16 + k4];
            acc += h.x * w[k4 * 4 + 0]; acc += h.y * w[k4 * 4 + 1];
            acc += h.z * w[k4 * 4 + 2]; acc += h.w * w[k4 * 4 + 3];
        }
#pragma unroll
        for (int k = 0; k < DB; k++) acc += sEA[elc][k] * w[64 + k];
        float r = tanha(acc);
        float v1 = __shfl_down_sync(0xffffffffu, r, 1);
        float v2 = __shfl_down_sync(0xffffffffu, r, 2);
        float v3 = __shfl_down_sync(0xffffffffu, r, 3);
        if (el < nE && (t & 3) == 0)
            red4(&g_h2[(size_t)sDst[el] * D2 + (f & 12)], make_float4(r, v1, v2, v3));
    }
}

// ---------------- K5: gate MLP + segment max + mean sum ----------------
#define K5_NPB 32
__global__ void __launch_bounds__(256)
k_gate(const float* __restrict__ Wg1, const float* __restrict__ bg1,
       const float* __restrict__ Wg2, const float* __restrict__ bg2,
       const float* __restrict__ Wg3, const float* __restrict__ bg3,
       const int* __restrict__ batch, int N) {
    __shared__ float sW1[16 * 64];
    __shared__ float sW2[64 * 32];
    __shared__ float sW3[32];
    __shared__ float sB1[64], sB2[32];
    __shared__ float sH[K5_NPB][17];
    __shared__ float sG1[K5_NPB][65];
    __shared__ float sG2[K5_NPB][33];
    int t = threadIdx.x;
    for (int i = t; i < 1024; i += 256) sW1[i] = Wg1[i];
    for (int i = t; i < 2048; i += 256) sW2[i] = Wg2[i];
    if (t < 32) sW3[t] = Wg3[t];
    if (t < 64) sB1[t] = bg1[t];
    if (t < 32) sB2[t] = bg2[t];
    int n0 = blockIdx.x * K5_NPB;
    int nN = min(K5_NPB, N - n0);
    for (int i = t; i < nN * 16; i += 256) sH[i >> 4][i & 15] = g_h2[(size_t)n0 * 16 + i];
    __syncthreads();
    {
        int f = t & 63;
        int r0 = (t >> 6) * 8;
#pragma unroll
        for (int r = 0; r < 8; r++) {
            int n = r0 + r;
            if (n < nN) {
                float acc = sB1[f];
#pragma unroll
                for (int k = 0; k < 16; k++) acc += sH[n][k] * sW1[k * 64 + f];
                sG1[n][f] = fmaxf(acc, 0.f);
            }
        }
    }
    __syncthreads();
    {
        int f2 = t & 31;
        int q0 = (t >> 5) * 4;
#pragma unroll
        for (int r = 0; r < 4; r++) {
            int n = q0 + r;
            if (n < nN) {
                float acc = sB2[f2];
#pragma unroll
                for (int j = 0; j < 64; j++) acc += sG1[n][j] * sW2[j * 32 + f2];
                sG2[n][f2] = fmaxf(acc, 0.f);
            }
        }
    }
    __syncthreads();
    if (t < 32) {
        float gv = 0.f;
        if (t < nN) {
            float acc = bg3[0];
#pragma unroll
            for (int j = 0; j < 32; j++) acc += sG2[t][j] * sW3[j];
            gv = acc;
            int i = n0 + t;
            g_gate[i] = acc;
            atomicMax(&g_gmax[batch[i]], fkey(acc));
        }
        float s = gv;
#pragma unroll
        for (int off = 16; off > 0; off >>= 1) s += __shfl_xor_sync(0xffffffffu, s, off);
        if (t == 0) atomicAdd(&g_meansum[0], s);
    }
}

// ---------------- K6: exp / segment sums / att ----------------
__global__ void k_soft1(const int* __restrict__ batch, int N, float invN,
                        float* __restrict__ d_att) {
    int i = blockIdx.x * blockDim.x + threadIdx.x;
    if (i >= N) return;
    float g = g_gate[i];
    int b = batch[i];
    float m = funkey(g_gmax[b]);
    float e = __expf(g - m);
    g_egate[i] = e;
    atomicAdd(&g_gsum[b], e);
    d_att[i] = g - g_meansum[0] * invN;
}

// ---------------- K7: attention-weighted embedding scatter (v4) ----------------
__global__ void k_scatter_emb(const int* __restrict__ batch, int N) {
    int i = blockIdx.x * blockDim.x + threadIdx.x;
    if (i >= N) return;
    int b = batch[i];
    float wt = g_egate[i] / (g_gsum[b] + 1e-16f);
    const float4* h = (const float4*)&g_h2[(size_t)i * 16];
    float* dst = &g_emb[b * 16];
#pragma unroll
    for (int j = 0; j < 4; j++) {
        float4 v = h[j];
        red4(dst + j * 4, make_float4(wt * v.x, wt * v.y, wt * v.z, wt * v.w));
    }
}

// ---------------- K8: head ----------------
__global__ void __launch_bounds__(256)
k_final(const float* __restrict__ Wsemi, const float* __restrict__ gamma,
        const float* __restrict__ beta, const float* __restrict__ bmean,
        const float* __restrict__ bvar, const float* __restrict__ Wf,
        const float* __restrict__ bf,
        float* __restrict__ outv, float* __restrict__ sigv,
        float* __restrict__ out1, int G) {
    __shared__ float sE[16];
    __shared__ float red[256];
    int g = blockIdx.x, t = threadIdx.x;
    if (t < 16) sE[t] = g_emb[g * 16 + t];
    __syncthreads();
    float part = 0.f;
    if (t < 200) {
        float acc = 0.f;
#pragma unroll
        for (int k = 0; k < 16; k++) acc += sE[k] * Wsemi[k * 200 + t];
        float o = (acc - bmean[t]) * rsqrtf(bvar[t] + 1e-5f) * gamma[t] + beta[t];
        out1[g * 200 + t] = o;
        part = o * Wf[t];
    }
    red[t] = part;
    __syncthreads();
    for (int s = 128; s > 0; s >>= 1) {
        if (t < s) red[t] += red[t + s];
        __syncthreads();
    }
    if (t == 0) {
        float o = red[0] + bf[0];
        outv[g] = o;
        sigv[g] = 1.f / (1.f + __expf(-o));
    }
}

// ---------------- launch ----------------
extern "C" void kernel_launch(void* const* d_in, const int* in_sizes, int n_in,
                              void* d_out, int out_size) {
    int idx = (in_sizes[4] == 1) ? 5 : 4;
    const int*   x      = (const int*)d_in[0];
    const int*   ei     = (const int*)d_in[1];
    const float* ea     = (const float*)d_in[2];
    const int*   batch  = (const int*)d_in[3];
    const float* embeds = (const float*)d_in[idx + 0];
    const float* Wn1 = (const float*)d_in[idx + 1];  const float* bn1 = (const float*)d_in[idx + 2];
    const float* Wr1 = (const float*)d_in[idx + 3];  const float* br1 = (const float*)d_in[idx + 4];
    const float* Wn2 = (const float*)d_in[idx + 5];  const float* bn2 = (const float*)d_in[idx + 6];
    const float* Wr2 = (const float*)d_in[idx + 7];  const float* br2 = (const float*)d_in[idx + 8];
    const float* Wg1 = (const float*)d_in[idx + 9];  const float* bg1 = (const float*)d_in[idx + 10];
    const float* Wg2 = (const float*)d_in[idx + 11]; const float* bg2 = (const float*)d_in[idx + 12];
    const float* Wg3 = (const float*)d_in[idx + 13]; const float* bg3 = (const float*)d_in[idx + 14];
    const float* Wsemi = (const float*)d_in[idx + 15];
    const float* gamma = (const float*)d_in[idx + 16];
    const float* beta  = (const float*)d_in[idx + 17];
    const float* bmean = (const float*)d_in[idx + 18];
    const float* bvar  = (const float*)d_in[idx + 19];
    const float* Wf    = (const float*)d_in[idx + 20];
    const float* bf    = (const float*)d_in[idx + 21];

    int N = in_sizes[0];
    int E = in_sizes[1] / 2;
    int G = (out_size - N) / 202;

    float* outv = (float*)d_out;
    float* sigv = outv + G;
    float* att  = outv + 2 * G;
    float* out1 = att + N;

    k_tables<<<1, 256>>>(embeds, Wn1, bn1, Wr1, br1);
    int initN = G * D2;
    k_init<<<(initN + 255) / 256, 256>>>(G);
    k_h1_init<<<(N * 16 + 255) / 256, 256>>>(x, N);
    k_conv1_edges<<<(E + K2_EPB - 1) / K2_EPB, 256>>>(ei, ea, x, Wn1, E);
    k_h2_root<<<(N + K3_NPB - 1) / K3_NPB, 256>>>(Wr2, br2, N);
    k_conv2_edges<<<(E + K4_EPB - 1) / K4_EPB, 256>>>(ei, ea, Wn2, bn2, E);
    k_gate<<<(N + K5_NPB - 1) / K5_NPB, 256>>>(Wg1, bg1, Wg2, bg2, Wg3, bg3, batch, N);
    k_soft1<<<(N + 255) / 256, 256>>>(batch, N, 1.f / (float)N, att);
    k_scatter_emb<<<(N + 255) / 256, 256>>>(batch, N);
    k_final<<<G, 256>>>(Wsemi, gamma, beta, bmean, bvar, Wf, bf, outv, sigv, out1, G);
}

// round 4
// speedup vs baseline: 2.2752x; 2.1063x over previous
#include <cuda_runtime.h>
#include <math.h>

#define D1 64
#define D2 16
#define DB 6
#define NMAX 250000
#define EMAX 2000000
#define GMAX 8192
#define NEMB 24

// ---------------- scratch ----------------
__device__ float    g_h1[NMAX * D1];      // 64 MB (h1 = tanh-root-table + scatter sum)
__device__ float    g_P[NMAX * D2];       // 16 MB (h1 @ Wn2[:64] + bn2)
__device__ float    g_h2[NMAX * D2];      // 16 MB
__device__ float    g_gate[NMAX];
__device__ float    g_egate[NMAX];
__device__ unsigned g_gmax[GMAX];
__device__ float    g_gsum[GMAX];
__device__ float    g_emb[GMAX * D2];
__device__ float    g_tabA1[NEMB * D1];   // embeds @ W_neg1[:64] + b_neg1
__device__ float    g_tabR1[NEMB * D1];   // tanh(embeds @ W_root1 + b_root1)
__device__ float    g_meansum[1];

// ---------------- helpers ----------------
__device__ __forceinline__ float tanha(float x) {
    float y;
    asm("tanh.approx.f32 %0, %1;" : "=f"(y) : "f"(x));
    return y;
}
__device__ __forceinline__ void red4(float* p, float4 v) {
    asm volatile("red.global.add.v4.f32 [%0], {%1,%2,%3,%4};"
                 :: "l"(p), "f"(v.x), "f"(v.y), "f"(v.z), "f"(v.w) : "memory");
}
__device__ __forceinline__ unsigned fkey(float f) {
    unsigned b = __float_as_uint(f);
    return (b & 0x80000000u) ? ~b : (b | 0x80000000u);
}
__device__ __forceinline__ float funkey(unsigned u) {
    unsigned b = (u & 0x80000000u) ? (u ^ 0x80000000u) : ~u;
    return __uint_as_float(b);
}

// ---------------- K0: precompute conv1 tables ----------------
__global__ void k_tables(const float* __restrict__ embeds,
                         const float* __restrict__ Wn1, const float* __restrict__ bn1,
                         const float* __restrict__ Wr1, const float* __restrict__ br1) {
    int t = threadIdx.x;
    for (int idx = t; idx < NEMB * D1; idx += blockDim.x) {
        int c = idx / D1, f = idx % D1;
        float a = bn1[f], r = br1[f];
        for (int k = 0; k < D1; k++) {
            float e = embeds[c * D1 + k];
            a += e * Wn1[k * D1 + f];
            r += e * Wr1[k * D1 + f];
        }
        g_tabA1[idx] = a;
        g_tabR1[idx] = tanhf(r);
    }
}

// ---------------- K_init ----------------
__global__ void k_init(int G) {
    int i = blockIdx.x * blockDim.x + threadIdx.x;
    if (i == 0) g_meansum[0] = 0.f;
    if (i < G) { g_gmax[i] = 0u; g_gsum[i] = 0.f; }
    if (i < G * D2) g_emb[i] = 0.f;
}

// ---------------- K1: h1 root part (float4) ----------------
__global__ void k_h1_init(const int* __restrict__ x, int N) {
    int t = blockIdx.x * blockDim.x + threadIdx.x;
    if (t >= N * 16) return;
    ((float4*)g_h1)[t] = ((const float4*)g_tabR1)[x[t >> 4] * 16 + (t & 15)];
}

// ---------------- K2: conv1 edge pass ----------------
#define K2_EPB 256
__global__ void __launch_bounds__(256)
k_conv1_edges(const int* __restrict__ ei, const float* __restrict__ ea,
              const int* __restrict__ x, const float* __restrict__ Wn1, int E) {
    __shared__ float4 sTab[NEMB * 16];
    __shared__ float4 sWbS[DB * 16];
    __shared__ float  sEA[K2_EPB][DB];
    __shared__ int    sDst[K2_EPB];
    __shared__ int    sC[K2_EPB];
    int t = threadIdx.x;
    const float4* tab4 = (const float4*)g_tabA1;
    for (int i = t; i < NEMB * 16; i += 256) sTab[i] = tab4[i];
    const float4* wb4 = (const float4*)(Wn1 + D1 * D1);
    if (t < DB * 16) sWbS[t] = wb4[t];
    int e0 = blockIdx.x * K2_EPB;
    int nE = min(K2_EPB, E - e0);
    if (t < nE) {
        sDst[t] = ei[e0 + t];
        sC[t]   = x[ei[E + e0 + t]];
    }
    for (int i = t; i < nE * DB; i += 256) sEA[i / DB][i % DB] = ea[e0 * DB + i];
    __syncthreads();

    int q = t & 15;
    float4 wb[DB];
#pragma unroll
    for (int k = 0; k < DB; k++) wb[k] = sWbS[k * 16 + q];

#pragma unroll
    for (int p = 0; p < K2_EPB / 16; p++) {
        int el = p * 16 + (t >> 4);
        if (el < nE) {
            float4 v = sTab[sC[el] * 16 + q];
#pragma unroll
            for (int k = 0; k < DB; k++) {
                float a = sEA[el][k];
                v.x += a * wb[k].x; v.y += a * wb[k].y;
                v.z += a * wb[k].z; v.w += a * wb[k].w;
            }
            v.x = tanha(v.x); v.y = tanha(v.y);
            v.z = tanha(v.z); v.w = tanha(v.w);
            red4(&g_h1[(size_t)sDst[el] * D1 + q * 4], v);
        }
    }
}

// ---------------- K3: node projection: P = h1@Wn2[:64]+bn2 ; h2 = tanh(h1@Wr2+br2) ----------------
#define KP_NPB 64
__global__ void __launch_bounds__(256, 2)
k_nodeproj(const float* __restrict__ Wn2, const float* __restrict__ bn2,
           const float* __restrict__ Wr2, const float* __restrict__ br2, int N) {
    __shared__ float4 sH[KP_NPB * 16];
    int t = threadIdx.x;
    int f = t & 31;            // 0..15 -> P column, 16..31 -> R column
    int c = f & 15;
    bool isP = (f < 16);
    const float* W = isP ? Wn2 : Wr2;
    float w[64];
#pragma unroll
    for (int k = 0; k < 64; k++) w[k] = W[k * D2 + c];
    float bias = isP ? bn2[c] : br2[c];

    int n0 = blockIdx.x * KP_NPB;
    int nN = min(KP_NPB, N - n0);
    const float4* h1v = (const float4*)g_h1;
    for (int i = t; i < nN * 16; i += 256) sH[i] = h1v[(size_t)n0 * 16 + i];
    __syncthreads();
#pragma unroll
    for (int p = 0; p < 8; p++) {
        int node = p * 8 + (t >> 5);
        if (node < nN) {
            float acc = bias;
#pragma unroll
            for (int k4 = 0; k4 < 16; k4++) {
                float4 h = sH[node * 16 + k4];
                acc += h.x * w[k4 * 4 + 0]; acc += h.y * w[k4 * 4 + 1];
                acc += h.z * w[k4 * 4 + 2]; acc += h.w * w[k4 * 4 + 3];
            }
            size_t o = (size_t)(n0 + node) * D2 + c;
            if (isP) g_P[o] = acc;
            else     g_h2[o] = tanhf(acc);
        }
    }
}

// ---------------- K4: conv2 edge pass (gather 16-f P, tiny MAC, scatter 16) ----------------
#define K4_EPB 256
__global__ void __launch_bounds__(256)
k_conv2_edges(const int* __restrict__ ei, const float* __restrict__ ea,
              const float* __restrict__ Wn2, int E) {
    __shared__ float sEA[K4_EPB][DB];
    __shared__ int   sDst[K4_EPB];
    __shared__ int   sSrc[K4_EPB];
    int t = threadIdx.x;
    int q = t & 3;  // quad of 4 output features
    float4 wb[DB];
#pragma unroll
    for (int k = 0; k < DB; k++)
        wb[k] = *(const float4*)&Wn2[(D1 + k) * D2 + q * 4];

    int e0 = blockIdx.x * K4_EPB;
    int nE = min(K4_EPB, E - e0);
    if (t < nE) {
        sDst[t] = ei[e0 + t];
        sSrc[t] = ei[E + e0 + t];
    }
    for (int i = t; i < nE * DB; i += 256) sEA[i / DB][i % DB] = ea[e0 * DB + i];
    __syncthreads();
    const float4* P4 = (const float4*)g_P;
#pragma unroll
    for (int p = 0; p < K4_EPB / 64; p++) {
        int el = p * 64 + (t >> 2);
        if (el < nE) {
            float4 acc = P4[(size_t)sSrc[el] * 4 + q];
#pragma unroll
            for (int k = 0; k < DB; k++) {
                float a = sEA[el][k];
                acc.x += a * wb[k].x; acc.y += a * wb[k].y;
                acc.z += a * wb[k].z; acc.w += a * wb[k].w;
            }
            acc.x = tanha(acc.x); acc.y = tanha(acc.y);
            acc.z = tanha(acc.z); acc.w = tanha(acc.w);
            red4(&g_h2[(size_t)sDst[el] * D2 + q * 4], acc);
        }
    }
}

// ---------------- K5: gate MLP + segment max + mean sum ----------------
#define K5_NPB 64
__global__ void __launch_bounds__(256)
k_gate(const float* __restrict__ Wg1, const float* __restrict__ bg1,
       const float* __restrict__ Wg2, const float* __restrict__ bg2,
       const float* __restrict__ Wg3, const float* __restrict__ bg3,
       const int* __restrict__ batch, int N) {
    __shared__ float sW1[16 * 64];
    __shared__ float sW2[64 * 32];
    __shared__ float sW3[32];
    __shared__ float sB1[64], sB2[32];
    __shared__ float sH[K5_NPB][17];
    __shared__ float sG1[K5_NPB][65];
    __shared__ float sG2[K5_NPB][33];
    int t = threadIdx.x;
    for (int i = t; i < 1024; i += 256) sW1[i] = Wg1[i];
    for (int i = t; i < 2048; i += 256) sW2[i] = Wg2[i];
    if (t < 32) sW3[t] = Wg3[t];
    if (t < 64) sB1[t] = bg1[t];
    if (t < 32) sB2[t] = bg2[t];
    int n0 = blockIdx.x * K5_NPB;
    int nN = min(K5_NPB, N - n0);
    for (int i = t; i < nN * 16; i += 256) sH[i >> 4][i & 15] = g_h2[(size_t)n0 * 16 + i];
    __syncthreads();
    {   // phase 1: 64 nodes x 64 feats
        int f = t & 63;
        int r0 = (t >> 6) * 16;
#pragma unroll
        for (int r = 0; r < 16; r++) {
            int n = r0 + r;
            if (n < nN) {
                float acc = sB1[f];
#pragma unroll
                for (int k = 0; k < 16; k++) acc += sH[n][k] * sW1[k * 64 + f];
                sG1[n][f] = fmaxf(acc, 0.f);
            }
        }
    }
    __syncthreads();
    {   // phase 2: 64 nodes x 32 feats
        int f2 = t & 31;
        int q0 = (t >> 5) * 8;
#pragma unroll
        for (int r = 0; r < 8; r++) {
            int n = q0 + r;
            if (n < nN) {
                float acc = sB2[f2];
#pragma unroll
                for (int j = 0; j < 64; j++) acc += sG1[n][j] * sW2[j * 32 + f2];
                sG2[n][f2] = fmaxf(acc, 0.f);
            }
        }
    }
    __syncthreads();
    if (t < 64) {   // phase 3: 2 warps, 1 node per thread
        float gv = 0.f;
        if (t < nN) {
            float acc = bg3[0];
#pragma unroll
            for (int j = 0; j < 32; j++) acc += sG2[t][j] * sW3[j];
            gv = acc;
            int i = n0 + t;
            g_gate[i] = acc;
            atomicMax(&g_gmax[batch[i]], fkey(acc));
        }
        float s = gv;
#pragma unroll
        for (int off = 16; off > 0; off >>= 1) s += __shfl_xor_sync(0xffffffffu, s, off);
        if ((t & 31) == 0) atomicAdd(&g_meansum[0], s);
    }
}

// ---------------- K6: exp / segment sums / att ----------------
__global__ void k_soft1(const int* __restrict__ batch, int N, float invN,
                        float* __restrict__ d_att) {
    int i = blockIdx.x * blockDim.x + threadIdx.x;
    if (i >= N) return;
    float g = g_gate[i];
    int b = batch[i];
    float m = funkey(g_gmax[b]);
    float e = __expf(g - m);
    g_egate[i] = e;
    atomicAdd(&g_gsum[b], e);
    d_att[i] = g - g_meansum[0] * invN;
}

// ---------------- K7: attention-weighted embedding scatter (v4) ----------------
__global__ void k_scatter_emb(const int* __restrict__ batch, int N) {
    int i = blockIdx.x * blockDim.x + threadIdx.x;
    if (i >= N) return;
    int b = batch[i];
    float wt = g_egate[i] / (g_gsum[b] + 1e-16f);
    const float4* h = (const float4*)&g_h2[(size_t)i * 16];
    float* dst = &g_emb[b * 16];
#pragma unroll
    for (int j = 0; j < 4; j++) {
        float4 v = h[j];
        red4(dst + j * 4, make_float4(wt * v.x, wt * v.y, wt * v.z, wt * v.w));
    }
}

// ---------------- K8: head ----------------
__global__ void __launch_bounds__(256)
k_final(const float* __restrict__ Wsemi, const float* __restrict__ gamma,
        const float* __restrict__ beta, const float* __restrict__ bmean,
        const float* __restrict__ bvar, const float* __restrict__ Wf,
        const float* __restrict__ bf,
        float* __restrict__ outv, float* __restrict__ sigv,
        float* __restrict__ out1, int G) {
    __shared__ float sE[16];
    __shared__ float red[256];
    int g = blockIdx.x, t = threadIdx.x;
    if (t < 16) sE[t] = g_emb[g * 16 + t];
    __syncthreads();
    float part = 0.f;
    if (t < 200) {
        float acc = 0.f;
#pragma unroll
        for (int k = 0; k < 16; k++) acc += sE[k] * Wsemi[k * 200 + t];
        float o = (acc - bmean[t]) * rsqrtf(bvar[t] + 1e-5f) * gamma[t] + beta[t];
        out1[g * 200 + t] = o;
        part = o * Wf[t];
    }
    red[t] = part;
    __syncthreads();
    for (int s = 128; s > 0; s >>= 1) {
        if (t < s) red[t] += red[t + s];
        __syncthreads();
    }
    if (t == 0) {
        float o = red[0] + bf[0];
        outv[g] = o;
        sigv[g] = 1.f / (1.f + __expf(-o));
    }
}

// ---------------- launch ----------------
extern "C" void kernel_launch(void* const* d_in, const int* in_sizes, int n_in,
                              void* d_out, int out_size) {
    int idx = (in_sizes[4] == 1) ? 5 : 4;
    const int*   x      = (const int*)d_in[0];
    const int*   ei     = (const int*)d_in[1];
    const float* ea     = (const float*)d_in[2];
    const int*   batch  = (const int*)d_in[3];
    const float* embeds = (const float*)d_in[idx + 0];
    const float* Wn1 = (const float*)d_in[idx + 1];  const float* bn1 = (const float*)d_in[idx + 2];
    const float* Wr1 = (const float*)d_in[idx + 3];  const float* br1 = (const float*)d_in[idx + 4];
    const float* Wn2 = (const float*)d_in[idx + 5];  const float* bn2 = (const float*)d_in[idx + 6];
    const float* Wr2 = (const float*)d_in[idx + 7];  const float* br2 = (const float*)d_in[idx + 8];
    const float* Wg1 = (const float*)d_in[idx + 9];  const float* bg1 = (const float*)d_in[idx + 10];
    const float* Wg2 = (const float*)d_in[idx + 11]; const float* bg2 = (const float*)d_in[idx + 12];
    const float* Wg3 = (const float*)d_in[idx + 13]; const float* bg3 = (const float*)d_in[idx + 14];
    const float* Wsemi = (const float*)d_in[idx + 15];
    const float* gamma = (const float*)d_in[idx + 16];
    const float* beta  = (const float*)d_in[idx + 17];
    const float* bmean = (const float*)d_in[idx + 18];
    const float* bvar  = (const float*)d_in[idx + 19];
    const float* Wf    = (const float*)d_in[idx + 20];
    const float* bf    = (const float*)d_in[idx + 21];

    int N = in_sizes[0];
    int E = in_sizes[1] / 2;
    int G = (out_size - N) / 202;

    float* outv = (float*)d_out;
    float* sigv = outv + G;
    float* att  = outv + 2 * G;
    float* out1 = att + N;

    k_tables<<<1, 256>>>(embeds, Wn1, bn1, Wr1, br1);
    int initN = G * D2;
    k_init<<<(initN + 255) / 256, 256>>>(G);
    k_h1_init<<<(N * 16 + 255) / 256, 256>>>(x, N);
    k_conv1_edges<<<(E + K2_EPB - 1) / K2_EPB, 256>>>(ei, ea, x, Wn1, E);
    k_nodeproj<<<(N + KP_NPB - 1) / KP_NPB, 256>>>(Wn2, bn2, Wr2, br2, N);
    k_conv2_edges<<<(E + K4_EPB - 1) / K4_EPB, 256>>>(ei, ea, Wn2, E);
    k_gate<<<(N + K5_NPB - 1) / K5_NPB, 256>>>(Wg1, bg1, Wg2, bg2, Wg3, bg3, batch, N);
    k_soft1<<<(N + 255) / 256, 256>>>(batch, N, 1.f / (float)N, att);
    k_scatter_emb<<<(N + 255) / 256, 256>>>(batch, N);
    k_final<<<G, 256>>>(Wsemi, gamma, beta, bmean, bvar, Wf, bf, outv, sigv, out1, G);
}

// round 7
// speedup vs baseline: 2.6496x; 1.1646x over previous
#include <cuda_runtime.h>
#include <math.h>

#define D1 64
#define D2 16
#define DB 6
#define NMAX 250000
#define EMAX 2000000
#define GMAX 8192
#define NEMB 24

typedef unsigned long long ull;

// ---------------- scratch (16B-aligned: accessed via v2/v4 loads) ----------------
__device__ __align__(16) float    g_h1[NMAX * D1];
__device__ __align__(16) float    g_P[NMAX * D2];
__device__ __align__(16) float    g_h2[NMAX * D2];
__device__ __align__(16) float    g_gate[NMAX];
__device__ __align__(16) float    g_egate[NMAX];
__device__ __align__(16) unsigned g_gmax[GMAX];
__device__ __align__(16) float    g_gsum[GMAX];
__device__ __align__(16) float    g_emb[GMAX * D2];
__device__ __align__(16) float    g_tabA1[NEMB * D1];
__device__ __align__(16) float    g_tabR1[NEMB * D1];
__device__ float                  g_meansum[1];

// ---------------- helpers ----------------
__device__ __forceinline__ float tanha(float x) {
    float y;
    asm("tanh.approx.f32 %0, %1;" : "=f"(y) : "f"(x));
    return y;
}
__device__ __forceinline__ void red4(float* p, float4 v) {
    asm volatile("red.global.add.v4.f32 [%0], {%1,%2,%3,%4};"
                 :: "l"(p), "f"(v.x), "f"(v.y), "f"(v.z), "f"(v.w) : "memory");
}
__device__ __forceinline__ ull pk(float a, float b) {
    ull r; asm("mov.b64 %0, {%1,%2};" : "=l"(r) : "f"(a), "f"(b)); return r;
}
__device__ __forceinline__ float2 upk(ull v) {
    float2 f; asm("mov.b64 {%0,%1}, %2;" : "=f"(f.x), "=f"(f.y) : "l"(v)); return f;
}
__device__ __forceinline__ ull ffma2(ull a, ull b, ull c) {
    ull r; asm("fma.rn.f32x2 %0, %1, %2, %3;" : "=l"(r) : "l"(a), "l"(b), "l"(c)); return r;
}
__device__ __forceinline__ unsigned fkey(float f) {
    unsigned b = __float_as_uint(f);
    return (b & 0x80000000u) ? ~b : (b | 0x80000000u);
}
__device__ __forceinline__ float funkey(unsigned u) {
    unsigned b = (u & 0x80000000u) ? (u ^ 0x80000000u) : ~u;
    return __uint_as_float(b);
}

// ---------------- K0: precompute conv1 tables ----------------
__global__ void k_tables(const float* __restrict__ embeds,
                         const float* __restrict__ Wn1, const float* __restrict__ bn1,
                         const float* __restrict__ Wr1, const float* __restrict__ br1) {
    int t = threadIdx.x;
    for (int idx = t; idx < NEMB * D1; idx += blockDim.x) {
        int c = idx / D1, f = idx % D1;
        float a = bn1[f], r = br1[f];
        for (int k = 0; k < D1; k++) {
            float e = embeds[c * D1 + k];
            a += e * Wn1[k * D1 + f];
            r += e * Wr1[k * D1 + f];
        }
        g_tabA1[idx] = a;
        g_tabR1[idx] = tanhf(r);
    }
}

// ---------------- K_init ----------------
__global__ void k_init(int G) {
    int i = blockIdx.x * blockDim.x + threadIdx.x;
    if (i == 0) g_meansum[0] = 0.f;
    if (i < G) { g_gmax[i] = 0u; g_gsum[i] = 0.f; }
    if (i < G * D2) g_emb[i] = 0.f;
}

// ---------------- K1: h1 root part (float4) ----------------
__global__ void k_h1_init(const int* __restrict__ x, int N) {
    int t = blockIdx.x * blockDim.x + threadIdx.x;
    if (t >= N * 16) return;
    ((float4*)g_h1)[t] = ((const float4*)g_tabR1)[x[t >> 4] * 16 + (t & 15)];
}

// ---------------- K2: conv1 edge pass (f32x2) ----------------
#define K2_EPB 256
__global__ void __launch_bounds__(256)
k_conv1_edges(const int* __restrict__ ei, const float* __restrict__ ea,
              const int* __restrict__ x, const float* __restrict__ Wn1, int E) {
    __shared__ __align__(16) ull  sTab2[NEMB * 32];          // tabA1 as pairs
    __shared__ __align__(16) ull  sEA2[K2_EPB][DB];          // {a,a} packed
    __shared__ int  sDst[K2_EPB];
    __shared__ int  sC[K2_EPB];
    int t = threadIdx.x;
    const ull* tab2 = (const ull*)g_tabA1;
    for (int i = t; i < NEMB * 32; i += 256) sTab2[i] = tab2[i];
    int e0 = blockIdx.x * K2_EPB;
    int nE = min(K2_EPB, E - e0);
    if (t < nE) {
        sDst[t] = ei[e0 + t];
        sC[t]   = x[ei[E + e0 + t]];
    }
    for (int i = t; i < nE * DB; i += 256) {
        float v = ea[e0 * DB + i];
        sEA2[i / DB][i % DB] = pk(v, v);
    }
    int q = t & 15;
    // weight pairs for this quad's 4 components (edge-attr rows of Wn1)
    ull wxy[DB], wzw[DB];
    const ull* Wn1u = (const ull*)Wn1;
#pragma unroll
    for (int k = 0; k < DB; k++) {
        int base = ((D1 + k) * D1 + q * 4) >> 1;
        wxy[k] = Wn1u[base];
        wzw[k] = Wn1u[base + 1];
    }
    __syncthreads();

#pragma unroll
    for (int p = 0; p < K2_EPB / 16; p++) {
        int el = p * 16 + (t >> 4);
        if (el < nE) {
            int c = sC[el];
            ull vxy = sTab2[c * 32 + q * 2];
            ull vzw = sTab2[c * 32 + q * 2 + 1];
#pragma unroll
            for (int k = 0; k < DB; k++) {
                ull a = sEA2[el][k];
                vxy = ffma2(a, wxy[k], vxy);
                vzw = ffma2(a, wzw[k], vzw);
            }
            float2 v01 = upk(vxy), v23 = upk(vzw);
            red4(&g_h1[(size_t)sDst[el] * D1 + q * 4],
                 make_float4(tanha(v01.x), tanha(v01.y), tanha(v23.x), tanha(v23.y)));
        }
    }
}

// ---------------- K3: node projection (f32x2) ----------------
#define KP_NPB 64
__global__ void __launch_bounds__(256, 2)
k_nodeproj(const float* __restrict__ Wn2, const float* __restrict__ bn2,
           const float* __restrict__ Wr2, const float* __restrict__ br2, int N) {
    __shared__ __align__(16) float4 sH[KP_NPB * 16];
    int t = threadIdx.x;
    int f = t & 31;            // 0..15 -> P column, 16..31 -> R column
    int c = f & 15;
    bool isP = (f < 16);
    const float* W = isP ? Wn2 : Wr2;
    ull wp[32];
#pragma unroll
    for (int k2 = 0; k2 < 32; k2++)
        wp[k2] = pk(W[(2 * k2) * D2 + c], W[(2 * k2 + 1) * D2 + c]);
    float bias = isP ? bn2[c] : br2[c];

    int n0 = blockIdx.x * KP_NPB;
    int nN = min(KP_NPB, N - n0);
    const float4* h1v = (const float4*)g_h1;
    for (int i = t; i < nN * 16; i += 256) sH[i] = h1v[(size_t)n0 * 16 + i];
    __syncthreads();
    const ull* sHu = (const ull*)sH;
#pragma unroll
    for (int p = 0; p < 8; p++) {
        int node = p * 8 + (t >> 5);
        if (node < nN) {
            ull acc = pk(bias, 0.f);
#pragma unroll
            for (int k2 = 0; k2 < 32; k2++)
                acc = ffma2(sHu[node * 32 + k2], wp[k2], acc);
            float2 a2 = upk(acc);
            float acc1 = a2.x + a2.y;
            size_t o = (size_t)(n0 + node) * D2 + c;
            if (isP) g_P[o] = acc1;
            else     g_h2[o] = tanhf(acc1);
        }
    }
}

// ---------------- K4: conv2 edge pass (f32x2) ----------------
#define K4_EPB 256
__global__ void __launch_bounds__(256)
k_conv2_edges(const int* __restrict__ ei, const float* __restrict__ ea,
              const float* __restrict__ Wn2, int E) {
    __shared__ __align__(16) ull  sEA2[K4_EPB][DB];
    __shared__ int  sDst[K4_EPB];
    __shared__ int  sSrc[K4_EPB];
    int t = threadIdx.x;
    int q = t & 3;  // quad of 4 output features
    ull wxy[DB], wzw[DB];
    const ull* Wn2u = (const ull*)Wn2;
#pragma unroll
    for (int k = 0; k < DB; k++) {
        int base = ((D1 + k) * D2 + q * 4) >> 1;
        wxy[k] = Wn2u[base];
        wzw[k] = Wn2u[base + 1];
    }
    int e0 = blockIdx.x * K4_EPB;
    int nE = min(K4_EPB, E - e0);
    if (t < nE) {
        sDst[t] = ei[e0 + t];
        sSrc[t] = ei[E + e0 + t];
    }
    for (int i = t; i < nE * DB; i += 256) {
        float v = ea[e0 * DB + i];
        sEA2[i / DB][i % DB] = pk(v, v);
    }
    __syncthreads();
    const float4* P4 = (const float4*)g_P;
#pragma unroll
    for (int p = 0; p < K4_EPB / 64; p++) {
        int el = p * 64 + (t >> 2);
        if (el < nE) {
            float4 pv = P4[(size_t)sSrc[el] * 4 + q];
            ull axy = pk(pv.x, pv.y);
            ull azw = pk(pv.z, pv.w);
#pragma unroll
            for (int k = 0; k < DB; k++) {
                ull a = sEA2[el][k];
                axy = ffma2(a, wxy[k], axy);
                azw = ffma2(a, wzw[k], azw);
            }
            float2 v01 = upk(axy), v23 = upk(azw);
            red4(&g_h2[(size_t)sDst[el] * D2 + q * 4],
                 make_float4(tanha(v01.x), tanha(v01.y), tanha(v23.x), tanha(v23.y)));
        }
    }
}

// ---------------- K5: gate MLP (register weights, f32x2) ----------------
#define K5_NPB 64
__global__ void __launch_bounds__(256)
k_gate(const float* __restrict__ Wg1, const float* __restrict__ bg1,
       const float* __restrict__ Wg2, const float* __restrict__ bg2,
       const float* __restrict__ Wg3, const float* __restrict__ bg3,
       const int* __restrict__ batch, int N) {
    __shared__ float sW3[32];
    __shared__ float sB3[1];
    __shared__ __align__(16) float sH[K5_NPB][18];
    __shared__ __align__(16) float sG1[K5_NPB][66];
    __shared__ float sG2[K5_NPB][33];
    int t = threadIdx.x;
    if (t < 32) sW3[t] = Wg3[t];
    if (t == 32) sB3[0] = bg3[0];
    int n0 = blockIdx.x * K5_NPB;
    int nN = min(K5_NPB, N - n0);
    for (int i = t; i < nN * 16; i += 256) sH[i >> 4][i & 15] = g_h2[(size_t)n0 * 16 + i];
    __syncthreads();
    {   // phase 1: 64 nodes x 64 feats, weights in regs
        int f = t & 63;
        float b1 = bg1[f];
        ull w1p[8];
#pragma unroll
        for (int k2 = 0; k2 < 8; k2++)
            w1p[k2] = pk(Wg1[(2 * k2) * 64 + f], Wg1[(2 * k2 + 1) * 64 + f]);
        int r0 = (t >> 6) * 16;
#pragma unroll
        for (int r = 0; r < 16; r++) {
            int n = r0 + r;
            if (n < nN) {
                const ull* hp = (const ull*)&sH[n][0];
                ull acc = pk(b1, 0.f);
#pragma unroll
                for (int k2 = 0; k2 < 8; k2++) acc = ffma2(hp[k2], w1p[k2], acc);
                float2 a2 = upk(acc);
                sG1[n][f] = fmaxf(a2.x + a2.y, 0.f);
            }
        }
    }
    __syncthreads();
    {   // phase 2: 64 nodes x 32 feats, weights in regs
        int f2 = t & 31;
        float b2 = bg2[f2];
        ull w2p[32];
#pragma unroll
        for (int j2 = 0; j2 < 32; j2++)
            w2p[j2] = pk(Wg2[(2 * j2) * 32 + f2], Wg2[(2 * j2 + 1) * 32 + f2]);
        int q0 = (t >> 5) * 8;
#pragma unroll
        for (int r = 0; r < 8; r++) {
            int n = q0 + r;
            if (n < nN) {
                const ull* gp = (const ull*)&sG1[n][0];
                ull acc = pk(b2, 0.f);
#pragma unroll
                for (int j2 = 0; j2 < 32; j2++) acc = ffma2(gp[j2], w2p[j2], acc);
                float2 a2 = upk(acc);
                sG2[n][f2] = fmaxf(a2.x + a2.y, 0.f);
            }
        }
    }
    __syncthreads();
    if (t < 64) {   // phase 3: 2 warps, 1 node per thread
        float gv = 0.f;
        if (t < nN) {
            float acc = sB3[0];
#pragma unroll
            for (int j = 0; j < 32; j++) acc += sG2[t][j] * sW3[j];
            gv = acc;
            int i = n0 + t;
            g_gate[i] = acc;
            atomicMax(&g_gmax[batch[i]], fkey(acc));
        }
        float s = gv;
#pragma unroll
        for (int off = 16; off > 0; off >>= 1) s += __shfl_xor_sync(0xffffffffu, s, off);
        if ((t & 31) == 0) atomicAdd(&g_meansum[0], s);
    }
}

// ---------------- K6: exp / segment sums / att ----------------
__global__ void k_soft1(const int* __restrict__ batch, int N, float invN,
                        float* __restrict__ d_att) {
    int i = blockIdx.x * blockDim.x + threadIdx.x;
    if (i >= N) return;
    float g = g_gate[i];
    int b = batch[i];
    float m = funkey(g_gmax[b]);
    float e = __expf(g - m);
    g_egate[i] = e;
    atomicAdd(&g_gsum[b], e);
    d_att[i] = g - g_meansum[0] * invN;
}

// ---------------- K7: attention-weighted embedding scatter ----------------
__global__ void k_scatter_emb(const int* __restrict__ batch, int N) {
    int i = blockIdx.x * blockDim.x + threadIdx.x;
    if (i >= N) return;
    int b = batch[i];
    float wt = g_egate[i] / (g_gsum[b] + 1e-16f);
    const float4* h = (const float4*)&g_h2[(size_t)i * 16];
    float* dst = &g_emb[b * 16];
#pragma unroll
    for (int j = 0; j < 4; j++) {
        float4 v = h[j];
        red4(dst + j * 4, make_float4(wt * v.x, wt * v.y, wt * v.z, wt * v.w));
    }
}

// ---------------- K8: head ----------------
__global__ void __launch_bounds__(256)
k_final(const float* __restrict__ Wsemi, const float* __restrict__ gamma,
        const float* __restrict__ beta, const float* __restrict__ bmean,
        const float* __restrict__ bvar, const float* __restrict__ Wf,
        const float* __restrict__ bf,
        float* __restrict__ outv, float* __restrict__ sigv,
        float* __restrict__ out1, int G) {
    __shared__ float sE[16];
    __shared__ float red[256];
    int g = blockIdx.x, t = threadIdx.x;
    if (t < 16) sE[t] = g_emb[g * 16 + t];
    __syncthreads();
    float part = 0.f;
    if (t < 200) {
        float acc = 0.f;
#pragma unroll
        for (int k = 0; k < 16; k++) acc += sE[k] * Wsemi[k * 200 + t];
        float o = (acc - bmean[t]) * rsqrtf(bvar[t] + 1e-5f) * gamma[t] + beta[t];
        out1[g * 200 + t] = o;
        part = o * Wf[t];
    }
    red[t] = part;
    __syncthreads();
    for (int s = 128; s > 0; s >>= 1) {
        if (t < s) red[t] += red[t + s];
        __syncthreads();
    }
    if (t == 0) {
        float o = red[0] + bf[0];
        outv[g] = o;
        sigv[g] = 1.f / (1.f + __expf(-o));
    }
}

// ---------------- launch ----------------
extern "C" void kernel_launch(void* const* d_in, const int* in_sizes, int n_in,
                              void* d_out, int out_size) {
    int idx = (in_sizes[4] == 1) ? 5 : 4;
    const int*   x      = (const int*)d_in[0];
    const int*   ei     = (const int*)d_in[1];
    const float* ea     = (const float*)d_in[2];
    const int*   batch  = (const int*)d_in[3];
    const float* embeds = (const float*)d_in[idx + 0];
    const float* Wn1 = (const float*)d_in[idx + 1];  const float* bn1 = (const float*)d_in[idx + 2];
    const float* Wr1 = (const float*)d_in[idx + 3];  const float* br1 = (const float*)d_in[idx + 4];
    const float* Wn2 = (const float*)d_in[idx + 5];  const float* bn2 = (const float*)d_in[idx + 6];
    const float* Wr2 = (const float*)d_in[idx + 7];  const float* br2 = (const float*)d_in[idx + 8];
    const float* Wg1 = (const float*)d_in[idx + 9];  const float* bg1 = (const float*)d_in[idx + 10];
    const float* Wg2 = (const float*)d_in[idx + 11]; const float* bg2 = (const float*)d_in[idx + 12];
    const float* Wg3 = (const float*)d_in[idx + 13]; const float* bg3 = (const float*)d_in[idx + 14];
    const float* Wsemi = (const float*)d_in[idx + 15];
    const float* gamma = (const float*)d_in[idx + 16];
    const float* beta  = (const float*)d_in[idx + 17];
    const float* bmean = (const float*)d_in[idx + 18];
    const float* bvar  = (const float*)d_in[idx + 19];
    const float* Wf    = (const float*)d_in[idx + 20];
    const float* bf    = (const float*)d_in[idx + 21];

    int N = in_sizes[0];
    int E = in_sizes[1] / 2;
    int G = (out_size - N) / 202;

    float* outv = (float*)d_out;
    float* sigv = outv + G;
    float* att  = outv + 2 * G;
    float* out1 = att + N;

    k_tables<<<1, 256>>>(embeds, Wn1, bn1, Wr1, br1);
    int initN = G * D2;
    k_init<<<(initN + 255) / 256, 256>>>(G);
    k_h1_init<<<(N * 16 + 255) / 256, 256>>>(x, N);
    k_conv1_edges<<<(E + K2_EPB - 1) / K2_EPB, 256>>>(ei, ea, x, Wn1, E);
    k_nodeproj<<<(N + KP_NPB - 1) / KP_NPB, 256>>>(Wn2, bn2, Wr2, br2, N);
    k_conv2_edges<<<(E + K4_EPB - 1) / K4_EPB, 256>>>(ei, ea, Wn2, E);
    k_gate<<<(N + K5_NPB - 1) / K5_NPB, 256>>>(Wg1, bg1, Wg2, bg2, Wg3, bg3, batch, N);
    k_soft1<<<(N + 255) / 256, 256>>>(batch, N, 1.f / (float)N, att);
    k_scatter_emb<<<(N + 255) / 256, 256>>>(batch, N);
    k_final<<<G, 256>>>(Wsemi, gamma, beta, bmean, bvar, Wf, bf, outv, sigv, out1, G);
}

// round 9
// speedup vs baseline: 2.7714x; 1.0460x over previous
#include <cuda_runtime.h>
#include <math.h>

#define D1 64
#define D2 16
#define DB 6
#define NMAX 250000
#define EMAX 2000000
#define GMAX 8192
#define NEMB 24

typedef unsigned long long ull;

// ---------------- scratch (16B-aligned: accessed via v2/v4 loads) ----------------
__device__ __align__(16) float    g_h1[NMAX * D1];
__device__ __align__(16) float    g_P[NMAX * D2];
__device__ __align__(16) float    g_h2[NMAX * D2];
__device__ __align__(16) float    g_gate[NMAX];
__device__ __align__(16) unsigned g_gmax[GMAX];
__device__ __align__(16) float    g_gsum[GMAX];
__device__ __align__(16) float    g_emb[GMAX * D2];
__device__ __align__(16) float    g_tabA1[NEMB * D1];
__device__ __align__(16) float    g_tabR1[NEMB * D1];
__device__ float                  g_meansum[1];

// ---------------- helpers ----------------
__device__ __forceinline__ float tanha(float x) {
    float y;
    asm("tanh.approx.f32 %0, %1;" : "=f"(y) : "f"(x));
    return y;
}
__device__ __forceinline__ void red4(float* p, float4 v) {
    asm volatile("red.global.add.v4.f32 [%0], {%1,%2,%3,%4};"
                 :: "l"(p), "f"(v.x), "f"(v.y), "f"(v.z), "f"(v.w) : "memory");
}
__device__ __forceinline__ ull pk(float a, float b) {
    ull r; asm("mov.b64 %0, {%1,%2};" : "=l"(r) : "f"(a), "f"(b)); return r;
}
__device__ __forceinline__ float2 upk(ull v) {
    float2 f; asm("mov.b64 {%0,%1}, %2;" : "=f"(f.x), "=f"(f.y) : "l"(v)); return f;
}
__device__ __forceinline__ ull ffma2(ull a, ull b, ull c) {
    ull r; asm("fma.rn.f32x2 %0, %1, %2, %3;" : "=l"(r) : "l"(a), "l"(b), "l"(c)); return r;
}
__device__ __forceinline__ unsigned fkey(float f) {
    unsigned b = __float_as_uint(f);
    return (b & 0x80000000u) ? ~b : (b | 0x80000000u);
}
__device__ __forceinline__ float funkey(unsigned u) {
    unsigned b = (u & 0x80000000u) ? (u ^ 0x80000000u) : ~u;
    return __uint_as_float(b);
}

// ---------------- K0: precompute conv1 tables ----------------
__global__ void k_tables(const float* __restrict__ embeds,
                         const float* __restrict__ Wn1, const float* __restrict__ bn1,
                         const float* __restrict__ Wr1, const float* __restrict__ br1) {
    int t = threadIdx.x;
    for (int idx = t; idx < NEMB * D1; idx += blockDim.x) {
        int c = idx / D1, f = idx % D1;
        float a = bn1[f], r = br1[f];
        for (int k = 0; k < D1; k++) {
            float e = embeds[c * D1 + k];
            a += e * Wn1[k * D1 + f];
            r += e * Wr1[k * D1 + f];
        }
        g_tabA1[idx] = a;
        g_tabR1[idx] = tanhf(r);
    }
}

// ---------------- K_init ----------------
__global__ void k_init(int G) {
    int i = blockIdx.x * blockDim.x + threadIdx.x;
    if (i == 0) g_meansum[0] = 0.f;
    if (i < G) { g_gmax[i] = 0u; g_gsum[i] = 0.f; }
    if (i < G * D2) g_emb[i] = 0.f;
}

// ---------------- K1: h1 root part (float4) ----------------
__global__ void k_h1_init(const int* __restrict__ x, int N) {
    int t = blockIdx.x * blockDim.x + threadIdx.x;
    if (t >= N * 16) return;
    ((float4*)g_h1)[t] = ((const float4*)g_tabR1)[x[t >> 4] * 16 + (t & 15)];
}

// ---------------- K2: conv1 edge pass (scalar FMA, lean LDS) ----------------
#define K2_EPB 256
__global__ void __launch_bounds__(256)
k_conv1_edges(const int* __restrict__ ei, const float* __restrict__ ea,
              const int* __restrict__ x, const float* __restrict__ Wn1, int E) {
    __shared__ __align__(16) float4 sTab[NEMB * 16];
    __shared__ __align__(8)  float2 sEA[K2_EPB][3];
    __shared__ int sDst[K2_EPB];
    __shared__ int sC[K2_EPB];
    int t = threadIdx.x;
    const float4* tab4 = (const float4*)g_tabA1;
    for (int i = t; i < NEMB * 16; i += 256) sTab[i] = tab4[i];
    int e0 = blockIdx.x * K2_EPB;
    int nE = min(K2_EPB, E - e0);
    if (t < nE) {
        sDst[t] = ei[e0 + t];
        sC[t]   = x[ei[E + e0 + t]];
    }
    const float2* ea2 = (const float2*)(ea + (size_t)e0 * DB);
    for (int i = t; i < nE * 3; i += 256) sEA[i / 3][i % 3] = ea2[i];

    int q = t & 15;
    float4 wb[DB];
#pragma unroll
    for (int k = 0; k < DB; k++)
        wb[k] = *(const float4*)&Wn1[(D1 + k) * D1 + q * 4];
    __syncthreads();

#pragma unroll
    for (int p = 0; p < K2_EPB / 16; p++) {
        int el = p * 16 + (t >> 4);
        if (el < nE) {
            float4 v = sTab[sC[el] * 16 + q];
            float2 a01 = sEA[el][0], a23 = sEA[el][1], a45 = sEA[el][2];
            v.x += a01.x * wb[0].x; v.y += a01.x * wb[0].y; v.z += a01.x * wb[0].z; v.w += a01.x * wb[0].w;
            v.x += a01.y * wb[1].x; v.y += a01.y * wb[1].y; v.z += a01.y * wb[1].z; v.w += a01.y * wb[1].w;
            v.x += a23.x * wb[2].x; v.y += a23.x * wb[2].y; v.z += a23.x * wb[2].z; v.w += a23.x * wb[2].w;
            v.x += a23.y * wb[3].x; v.y += a23.y * wb[3].y; v.z += a23.y * wb[3].z; v.w += a23.y * wb[3].w;
            v.x += a45.x * wb[4].x; v.y += a45.x * wb[4].y; v.z += a45.x * wb[4].z; v.w += a45.x * wb[4].w;
            v.x += a45.y * wb[5].x; v.y += a45.y * wb[5].y; v.z += a45.y * wb[5].z; v.w += a45.y * wb[5].w;
            red4(&g_h1[(size_t)sDst[el] * D1 + q * 4],
                 make_float4(tanha(v.x), tanha(v.y), tanha(v.z), tanha(v.w)));
        }
    }
}

// ---------------- K3: node projection (f32x2) ----------------
#define KP_NPB 64
__global__ void __launch_bounds__(256, 2)
k_nodeproj(const float* __restrict__ Wn2, const float* __restrict__ bn2,
           const float* __restrict__ Wr2, const float* __restrict__ br2, int N) {
    __shared__ __align__(16) float4 sH[KP_NPB * 16];
    int t = threadIdx.x;
    int f = t & 31;            // 0..15 -> P column, 16..31 -> R column
    int c = f & 15;
    bool isP = (f < 16);
    const float* W = isP ? Wn2 : Wr2;
    ull wp[32];
#pragma unroll
    for (int k2 = 0; k2 < 32; k2++)
        wp[k2] = pk(W[(2 * k2) * D2 + c], W[(2 * k2 + 1) * D2 + c]);
    float bias = isP ? bn2[c] : br2[c];

    int n0 = blockIdx.x * KP_NPB;
    int nN = min(KP_NPB, N - n0);
    const float4* h1v = (const float4*)g_h1;
    for (int i = t; i < nN * 16; i += 256) sH[i] = h1v[(size_t)n0 * 16 + i];
    __syncthreads();
    const ull* sHu = (const ull*)sH;
#pragma unroll
    for (int p = 0; p < 8; p++) {
        int node = p * 8 + (t >> 5);
        if (node < nN) {
            ull acc = pk(bias, 0.f);
#pragma unroll
            for (int k2 = 0; k2 < 32; k2++)
                acc = ffma2(sHu[node * 32 + k2], wp[k2], acc);
            float2 a2 = upk(acc);
            float acc1 = a2.x + a2.y;
            size_t o = (size_t)(n0 + node) * D2 + c;
            if (isP) g_P[o] = acc1;
            else     g_h2[o] = tanhf(acc1);
        }
    }
}

// ---------------- K4: conv2 edge pass (f32x2) ----------------
#define K4_EPB 256
__global__ void __launch_bounds__(256)
k_conv2_edges(const int* __restrict__ ei, const float* __restrict__ ea,
              const float* __restrict__ Wn2, int E) {
    __shared__ __align__(16) ull  sEA2[K4_EPB][DB];
    __shared__ int  sDst[K4_EPB];
    __shared__ int  sSrc[K4_EPB];
    int t = threadIdx.x;
    int q = t & 3;  // quad of 4 output features
    ull wxy[DB], wzw[DB];
    const ull* Wn2u = (const ull*)Wn2;
#pragma unroll
    for (int k = 0; k < DB; k++) {
        int base = ((D1 + k) * D2 + q * 4) >> 1;
        wxy[k] = Wn2u[base];
        wzw[k] = Wn2u[base + 1];
    }
    int e0 = blockIdx.x * K4_EPB;
    int nE = min(K4_EPB, E - e0);
    if (t < nE) {
        sDst[t] = ei[e0 + t];
        sSrc[t] = ei[E + e0 + t];
    }
    for (int i = t; i < nE * DB; i += 256) {
        float v = ea[(size_t)e0 * DB + i];
        sEA2[i / DB][i % DB] = pk(v, v);
    }
    __syncthreads();
    const float4* P4 = (const float4*)g_P;
#pragma unroll
    for (int p = 0; p < K4_EPB / 64; p++) {
        int el = p * 64 + (t >> 2);
        if (el < nE) {
            float4 pv = P4[(size_t)sSrc[el] * 4 + q];
            ull axy = pk(pv.x, pv.y);
            ull azw = pk(pv.z, pv.w);
#pragma unroll
            for (int k = 0; k < DB; k++) {
                ull a = sEA2[el][k];
                axy = ffma2(a, wxy[k], axy);
                azw = ffma2(a, wzw[k], azw);
            }
            float2 v01 = upk(axy), v23 = upk(azw);
            red4(&g_h2[(size_t)sDst[el] * D2 + q * 4],
                 make_float4(tanha(v01.x), tanha(v01.y), tanha(v23.x), tanha(v23.y)));
        }
    }
}

// ---------------- K5: gate MLP (register weights, f32x2) ----------------
#define K5_NPB 64
__global__ void __launch_bounds__(256)
k_gate(const float* __restrict__ Wg1, const float* __restrict__ bg1,
       const float* __restrict__ Wg2, const float* __restrict__ bg2,
       const float* __restrict__ Wg3, const float* __restrict__ bg3,
       const int* __restrict__ batch, int N) {
    __shared__ float sW3[32];
    __shared__ float sB3[1];
    __shared__ __align__(16) float sH[K5_NPB][18];
    __shared__ __align__(16) float sG1[K5_NPB][66];
    __shared__ float sG2[K5_NPB][33];
    int t = threadIdx.x;
    if (t < 32) sW3[t] = Wg3[t];
    if (t == 32) sB3[0] = bg3[0];
    int n0 = blockIdx.x * K5_NPB;
    int nN = min(K5_NPB, N - n0);
    for (int i = t; i < nN * 16; i += 256) sH[i >> 4][i & 15] = g_h2[(size_t)n0 * 16 + i];
    __syncthreads();
    {   // phase 1: 64 nodes x 64 feats, weights in regs
        int f = t & 63;
        float b1 = bg1[f];
        ull w1p[8];
#pragma unroll
        for (int k2 = 0; k2 < 8; k2++)
            w1p[k2] = pk(Wg1[(2 * k2) * 64 + f], Wg1[(2 * k2 + 1) * 64 + f]);
        int r0 = (t >> 6) * 16;
#pragma unroll
        for (int r = 0; r < 16; r++) {
            int n = r0 + r;
            if (n < nN) {
                const ull* hp = (const ull*)&sH[n][0];
                ull acc = pk(b1, 0.f);
#pragma unroll
                for (int k2 = 0; k2 < 8; k2++) acc = ffma2(hp[k2], w1p[k2], acc);
                float2 a2 = upk(acc);
                sG1[n][f] = fmaxf(a2.x + a2.y, 0.f);
            }
        }
    }
    __syncthreads();
    {   // phase 2: 64 nodes x 32 feats, weights in regs
        int f2 = t & 31;
        float b2 = bg2[f2];
        ull w2p[32];
#pragma unroll
        for (int j2 = 0; j2 < 32; j2++)
            w2p[j2] = pk(Wg2[(2 * j2) * 32 + f2], Wg2[(2 * j2 + 1) * 32 + f2]);
        int q0 = (t >> 5) * 8;
#pragma unroll
        for (int r = 0; r < 8; r++) {
            int n = q0 + r;
            if (n < nN) {
                const ull* gp = (const ull*)&sG1[n][0];
                ull acc = pk(b2, 0.f);
#pragma unroll
                for (int j2 = 0; j2 < 32; j2++) acc = ffma2(gp[j2], w2p[j2], acc);
                float2 a2 = upk(acc);
                sG2[n][f2] = fmaxf(a2.x + a2.y, 0.f);
            }
        }
    }
    __syncthreads();
    if (t < 64) {   // phase 3: 2 warps, 1 node per thread
        float gv = 0.f;
        if (t < nN) {
            float acc = sB3[0];
#pragma unroll
            for (int j = 0; j < 32; j++) acc += sG2[t][j] * sW3[j];
            gv = acc;
            int i = n0 + t;
            g_gate[i] = acc;
            atomicMax(&g_gmax[batch[i]], fkey(acc));
        }
        float s = gv;
#pragma unroll
        for (int off = 16; off > 0; off >>= 1) s += __shfl_xor_sync(0xffffffffu, s, off);
        if ((t & 31) == 0) atomicAdd(&g_meansum[0], s);
    }
}

// ---------------- K6: fused softmax-exp + unnormalized scatter + att ----------------
__global__ void k_soft_scatter(const int* __restrict__ batch, int N, float invN,
                               float* __restrict__ d_att) {
    int i = blockIdx.x * blockDim.x + threadIdx.x;
    if (i >= N) return;
    float g = g_gate[i];
    int b = batch[i];
    float m = funkey(g_gmax[b]);
    float e = __expf(g - m);
    d_att[i] = g - g_meansum[0] * invN;
    atomicAdd(&g_gsum[b], e);
    const float4* h = (const float4*)&g_h2[(size_t)i * 16];
    float* dst = &g_emb[b * 16];
#pragma unroll
    for (int j = 0; j < 4; j++) {
        float4 v = h[j];
        red4(dst + j * 4, make_float4(e * v.x, e * v.y, e * v.z, e * v.w));
    }
}

// ---------------- K8: head (with softmax normalization folded in) ----------------
__global__ void __launch_bounds__(256)
k_final(const float* __restrict__ Wsemi, const float* __restrict__ gamma,
        const float* __restrict__ beta, const float* __restrict__ bmean,
        const float* __restrict__ bvar, const float* __restrict__ Wf,
        const float* __restrict__ bf,
        float* __restrict__ outv, float* __restrict__ sigv,
        float* __restrict__ out1, int G) {
    __shared__ float sE[16];
    __shared__ float red[256];
    int g = blockIdx.x, t = threadIdx.x;
    if (t < 16) {
        float inv = 1.f / (g_gsum[g] + 1e-16f);
        sE[t] = g_emb[g * 16 + t] * inv;
    }
    __syncthreads();
    float part = 0.f;
    if (t < 200) {
        float acc = 0.f;
#pragma unroll
        for (int k = 0; k < 16; k++) acc += sE[k] * Wsemi[k * 200 + t];
        float o = (acc - bmean[t]) * rsqrtf(bvar[t] + 1e-5f) * gamma[t] + beta[t];
        out1[g * 200 + t] = o;
        part = o * Wf[t];
    }
    red[t] = part;
    __syncthreads();
    for (int s = 128; s > 0; s >>= 1) {
        if (t < s) red[t] += red[t + s];
        __syncthreads();
    }
    if (t == 0) {
        float o = red[0] + bf[0];
        outv[g] = o;
        sigv[g] = 1.f / (1.f + __expf(-o));
    }
}

// ---------------- launch ----------------
extern "C" void kernel_launch(void* const* d_in, const int* in_sizes, int n_in,
                              void* d_out, int out_size) {
    int idx = (in_sizes[4] == 1) ? 5 : 4;
    const int*   x      = (const int*)d_in[0];
    const int*   ei     = (const int*)d_in[1];
    const float* ea     = (const float*)d_in[2];
    const int*   batch  = (const int*)d_in[3];
    const float* embeds = (const float*)d_in[idx + 0];
    const float* Wn1 = (const float*)d_in[idx + 1];  const float* bn1 = (const float*)d_in[idx + 2];
    const float* Wr1 = (const float*)d_in[idx + 3];  const float* br1 = (const float*)d_in[idx + 4];
    const float* Wn2 = (const float*)d_in[idx + 5];  const float* bn2 = (const float*)d_in[idx + 6];
    const float* Wr2 = (const float*)d_in[idx + 7];  const float* br2 = (const float*)d_in[idx + 8];
    const float* Wg1 = (const float*)d_in[idx + 9];  const float* bg1 = (const float*)d_in[idx + 10];
    const float* Wg2 = (const float*)d_in[idx + 11]; const float* bg2 = (const float*)d_in[idx + 12];
    const float* Wg3 = (const float*)d_in[idx + 13]; const float* bg3 = (const float*)d_in[idx + 14];
    const float* Wsemi = (const float*)d_in[idx + 15];
    const float* gamma = (const float*)d_in[idx + 16];
    const float* beta  = (const float*)d_in[idx + 17];
    const float* bmean = (const float*)d_in[idx + 18];
    const float* bvar  = (const float*)d_in[idx + 19];
    const float* Wf    = (const float*)d_in[idx + 20];
    const float* bf    = (const float*)d_in[idx + 21];

    int N = in_sizes[0];
    int E = in_sizes[1] / 2;
    int G = (out_size - N) / 202;

    float* outv = (float*)d_out;
    float* sigv = outv + G;
    float* att  = outv + 2 * G;
    float* out1 = att + N;

    k_tables<<<1, 256>>>(embeds, Wn1, bn1, Wr1, br1);
    int initN = G * D2;
    k_init<<<(initN + 255) / 256, 256>>>(G);
    k_h1_init<<<(N * 16 + 255) / 256, 256>>>(x, N);
    k_conv1_edges<<<(E + K2_EPB - 1) / K2_EPB, 256>>>(ei, ea, x, Wn1, E);
    k_nodeproj<<<(N + KP_NPB - 1) / KP_NPB, 256>>>(Wn2, bn2, Wr2, br2, N);
    k_conv2_edges<<<(E + K4_EPB - 1) / K4_EPB, 256>>>(ei, ea, Wn2, E);
    k_gate<<<(N + K5_NPB - 1) / K5_NPB, 256>>>(Wg1, bg1, Wg2, bg2, Wg3, bg3, batch, N);
    k_soft_scatter<<<(N + 255) / 256, 256>>>(batch, N, 1.f / (float)N, att);
    k_final<<<G, 256>>>(Wsemi, gamma, beta, bmean, bvar, Wf, bf, outv, sigv, out1, G);
}